// round 1
// baseline (speedup 1.0000x reference)
#include <cuda_runtime.h>

#define NEMB 50
#define EDIM 192
#define ESTRIDE 52   // floats per smem row: 52*4 = 208 B, multiple of 16 B

__device__ double g_loss_sum;

static __device__ __forceinline__ unsigned long long pack2(float lo, float hi) {
    unsigned long long r;
    asm("mov.b64 %0, {%1, %2};" : "=l"(r) : "f"(lo), "f"(hi));
    return r;
}
static __device__ __forceinline__ void unpack2(unsigned long long v, float& lo, float& hi) {
    asm("mov.b64 {%0, %1}, %2;" : "=f"(lo), "=f"(hi) : "l"(v));
}
// Packed dual-FMA: 2 fp32 FMAs per instruction (FFMA2). PTX-only form.
static __device__ __forceinline__ unsigned long long fma2(unsigned long long a,
                                                          unsigned long long b,
                                                          unsigned long long c) {
    unsigned long long d;
    asm("fma.rn.f32x2 %0, %1, %2, %3;" : "=l"(d) : "l"(a), "l"(b), "l"(c));
    return d;
}

__global__ void vq_reset_kernel() { g_loss_sum = 0.0; }

__global__ __launch_bounds__(256) void vq_main_kernel(
        const float* __restrict__ x, const float* __restrict__ e,
        float* __restrict__ out, int n) {
    // Codebook transposed in smem: Et[k][j], j contiguous -> 16B vector LDS gives
    // 4 adjacent codebook entries at dim k (2 packed f32x2 operands).
    __shared__ __align__(16) float Et[EDIM * ESTRIDE];
    __shared__ float see[NEMB];
    __shared__ float wsum[8];

    const int tid = threadIdx.x;

    for (int i = tid; i < NEMB * EDIM; i += 256) {
        int j = i / EDIM, k = i - j * EDIM;      // e is [j][k] row-major, coalesced read
        Et[k * ESTRIDE + j] = e[i];
    }
    __syncthreads();
    if (tid < NEMB) {
        float s = 0.f;
        #pragma unroll 4
        for (int k = 0; k < EDIM; ++k) {
            float v = Et[k * ESTRIDE + tid];
            s = fmaf(v, v, s);
        }
        see[tid] = s;
    }
    __syncthreads();

    const int row = blockIdx.x * 256 + tid;
    float lsum = 0.f;

    if (row < n) {
        unsigned long long acc[25];              // 25 f32x2 accumulators = 50 dots
        #pragma unroll
        for (int p = 0; p < 25; ++p) acc[p] = 0ULL;

        float s0 = 0.f, s1 = 0.f;                // ||x||^2 partials
        const float4* xr = reinterpret_cast<const float4*>(x + (size_t)row * EDIM);

        #pragma unroll 1
        for (int k0 = 0; k0 < EDIM / 4; ++k0) {
            const float4 xv = __ldg(xr + k0);
            s0 = fmaf(xv.x, xv.x, s0); s1 = fmaf(xv.y, xv.y, s1);
            s0 = fmaf(xv.z, xv.z, s0); s1 = fmaf(xv.w, xv.w, s1);
            const float xk[4] = {xv.x, xv.y, xv.z, xv.w};
            #pragma unroll
            for (int c = 0; c < 4; ++c) {
                const int k = k0 * 4 + c;
                const unsigned long long xx = pack2(xk[c], xk[c]);
                const float* erow = &Et[k * ESTRIDE];
                #pragma unroll
                for (int jj = 0; jj < 12; ++jj) { // j = 0..47 in groups of 4
                    ulonglong2 ev = *reinterpret_cast<const ulonglong2*>(erow + jj * 4);
                    acc[2 * jj]     = fma2(xx, ev.x, acc[2 * jj]);
                    acc[2 * jj + 1] = fma2(xx, ev.y, acc[2 * jj + 1]);
                }
                unsigned long long ev2 =
                    *reinterpret_cast<const unsigned long long*>(erow + 48); // j = 48,49
                acc[24] = fma2(xx, ev2, acc[24]);
            }
        }
        const float sxx = s0 + s1;

        // argmin with JAX-matching fp32 rounding: (sxx + see_j) - 2*dot_j,
        // first-index tie-break (strict <, ascending j).
        float bestd = 3.402823466e38f;
        int bestj = 0;
        #pragma unroll
        for (int p = 0; p < 25; ++p) {
            float d0, d1;
            unpack2(acc[p], d0, d1);
            float t0 = __fsub_rn(__fadd_rn(sxx, see[2 * p]),     2.0f * d0);
            float t1 = __fsub_rn(__fadd_rn(sxx, see[2 * p + 1]), 2.0f * d1);
            if (t0 < bestd) { bestd = t0; bestj = 2 * p; }
            if (t1 < bestd) { bestd = t1; bestj = 2 * p + 1; }
        }

        out[(size_t)n * EDIM + row] = (float)bestj;   // indices as output dtype

        // Phase 2: straight-through output x + (q - x) (matches reference rounding)
        // + commit-loss partial. x row is L1-hot from phase 1; the 50 codebook
        // rows (38 KB) stay L1-resident.
        const float4* er = reinterpret_cast<const float4*>(e + (size_t)bestj * EDIM);
        float4* oq = reinterpret_cast<float4*>(out + (size_t)row * EDIM);
        #pragma unroll 1
        for (int k0 = 0; k0 < EDIM / 4; ++k0) {
            const float4 q  = __ldg(er + k0);
            const float4 xv = __ldg(xr + k0);
            float dx = __fsub_rn(q.x, xv.x), dy = __fsub_rn(q.y, xv.y);
            float dz = __fsub_rn(q.z, xv.z), dw = __fsub_rn(q.w, xv.w);
            lsum = fmaf(dx, dx, lsum); lsum = fmaf(dy, dy, lsum);
            lsum = fmaf(dz, dz, lsum); lsum = fmaf(dw, dw, lsum);
            float4 o;
            o.x = __fadd_rn(xv.x, dx); o.y = __fadd_rn(xv.y, dy);
            o.z = __fadd_rn(xv.z, dz); o.w = __fadd_rn(xv.w, dw);
            oq[k0] = o;
        }
    }

    // Block-level loss reduction (all threads participate; inactive rows add 0)
    #pragma unroll
    for (int off = 16; off > 0; off >>= 1)
        lsum += __shfl_down_sync(0xffffffffu, lsum, off);
    if ((tid & 31) == 0) wsum[tid >> 5] = lsum;
    __syncthreads();
    if (tid == 0) {
        float bs = 0.f;
        #pragma unroll
        for (int w = 0; w < 8; ++w) bs += wsum[w];
        atomicAdd(&g_loss_sum, (double)bs);
    }
}

__global__ void vq_finalize_kernel(float* __restrict__ out, int n) {
    double mean = g_loss_sum / ((double)n * (double)EDIM);
    out[(size_t)n * EDIM + n]     = (float)(1.25 * mean);  // (1 + BETA) * mean
    out[(size_t)n * EDIM + n + 1] = 0.0f;                  // contrastloss
}

extern "C" void kernel_launch(void* const* d_in, const int* in_sizes, int n_in,
                              void* d_out, int out_size) {
    (void)n_in; (void)out_size;
    const float* x = (const float*)d_in[0];   // inputs  [N, 192] fp32
    const float* e = (const float*)d_in[1];   // embed_w [50, 192] fp32
    float* out = (float*)d_out;               // [N*192 | N | 1 | 1] fp32
    const int n = in_sizes[0] / EDIM;

    vq_reset_kernel<<<1, 1>>>();
    vq_main_kernel<<<(n + 255) / 256, 256>>>(x, e, out, n);
    vq_finalize_kernel<<<1, 1>>>(out, n);
}

// round 2
// speedup vs baseline: 1.3111x; 1.3111x over previous
#include <cuda_runtime.h>

#define NEMB 50
#define EDIM 192
#define ESTRIDE 52   // floats per smem row of Et: 208 B, 16 B-aligned

__device__ double g_loss_sum;        // zero-initialized at module load
__device__ unsigned int g_done;      // zero-initialized at module load

static __device__ __forceinline__ unsigned long long pack2s(float v) {
    unsigned long long r;
    asm("mov.b64 %0, {%1, %1};" : "=l"(r) : "f"(v));
    return r;
}
static __device__ __forceinline__ void unpack2(unsigned long long v, float& lo, float& hi) {
    asm("mov.b64 {%0, %1}, %2;" : "=f"(lo), "=f"(hi) : "l"(v));
}
// Packed dual-FMA (FFMA2): 2 fp32 FMAs per instruction. PTX-only form.
static __device__ __forceinline__ unsigned long long fma2(unsigned long long a,
                                                          unsigned long long b,
                                                          unsigned long long c) {
    unsigned long long d;
    asm("fma.rn.f32x2 %0, %1, %2, %3;" : "=l"(d) : "l"(a), "l"(b), "l"(c));
    return d;
}

// One fused kernel: 2 rows per thread, 128 threads/block => 256 rows/block.
__global__ __launch_bounds__(128) void vq_main_kernel(
        const float* __restrict__ x, const float* __restrict__ e,
        float* __restrict__ out, int n) {
    __shared__ __align__(16) float Et[EDIM * ESTRIDE];  // Et[k][j], j contiguous
    __shared__ float see[NEMB];
    __shared__ float wsum[4];

    const int tid = threadIdx.x;

    for (int i = tid; i < NEMB * EDIM; i += 128) {
        int j = i / EDIM, k = i - j * EDIM;              // e is [j][k] row-major
        Et[k * ESTRIDE + j] = e[i];
    }
    __syncthreads();
    if (tid < NEMB) {
        float s = 0.f;
        #pragma unroll 4
        for (int k = 0; k < EDIM; ++k) {
            float v = Et[k * ESTRIDE + tid];
            s = fmaf(v, v, s);
        }
        see[tid] = s;
    }
    __syncthreads();

    const int base = blockIdx.x * 256;
    const int r0 = base + tid;
    const int r1 = base + 128 + tid;
    const bool v0 = (r0 < n);
    const bool v1 = (r1 < n);
    // Clamp pointers so the compute path is branch-free; stores are guarded.
    const float4* xr0 = reinterpret_cast<const float4*>(x + (size_t)(v0 ? r0 : 0) * EDIM);
    const float4* xr1 = reinterpret_cast<const float4*>(x + (size_t)(v1 ? r1 : 0) * EDIM);

    float lsum = 0.f;

    {
        unsigned long long acc0[25], acc1[25];           // 25 f32x2 each = 50 dots/row
        #pragma unroll
        for (int p = 0; p < 25; ++p) { acc0[p] = 0ULL; acc1[p] = 0ULL; }

        float sa0 = 0.f, sa1 = 0.f, sb0 = 0.f, sb1 = 0.f;

        #pragma unroll 1
        for (int k0 = 0; k0 < EDIM / 4; ++k0) {
            const float4 a = __ldg(xr0 + k0);
            const float4 b = __ldg(xr1 + k0);
            sa0 = fmaf(a.x, a.x, sa0); sa1 = fmaf(a.y, a.y, sa1);
            sa0 = fmaf(a.z, a.z, sa0); sa1 = fmaf(a.w, a.w, sa1);
            sb0 = fmaf(b.x, b.x, sb0); sb1 = fmaf(b.y, b.y, sb1);
            sb0 = fmaf(b.z, b.z, sb0); sb1 = fmaf(b.w, b.w, sb1);
            const float xa[4] = {a.x, a.y, a.z, a.w};
            const float xb[4] = {b.x, b.y, b.z, b.w};
            #pragma unroll
            for (int c = 0; c < 4; ++c) {
                const unsigned long long pa = pack2s(xa[c]);
                const unsigned long long pb = pack2s(xb[c]);
                const float* erow = &Et[(k0 * 4 + c) * ESTRIDE];
                #pragma unroll
                for (int jj = 0; jj < 12; ++jj) {        // j = 0..47, groups of 4
                    ulonglong2 ev = *reinterpret_cast<const ulonglong2*>(erow + jj * 4);
                    acc0[2 * jj]     = fma2(pa, ev.x, acc0[2 * jj]);
                    acc1[2 * jj]     = fma2(pb, ev.x, acc1[2 * jj]);
                    acc0[2 * jj + 1] = fma2(pa, ev.y, acc0[2 * jj + 1]);
                    acc1[2 * jj + 1] = fma2(pb, ev.y, acc1[2 * jj + 1]);
                }
                const unsigned long long ev2 =
                    *reinterpret_cast<const unsigned long long*>(erow + 48); // j = 48,49
                acc0[24] = fma2(pa, ev2, acc0[24]);
                acc1[24] = fma2(pb, ev2, acc1[24]);
            }
        }
        const float sxx0 = sa0 + sa1;
        const float sxx1 = sb0 + sb1;

        // argmin, JAX fp32 rounding: (||x||^2 + ||e||^2) - 2*dot, first-index ties.
        float bd0 = 3.402823466e38f, bd1 = 3.402823466e38f;
        int bj0 = 0, bj1 = 0;
        #pragma unroll
        for (int p = 0; p < 25; ++p) {
            float d0, d1, f0, f1;
            unpack2(acc0[p], d0, d1);
            unpack2(acc1[p], f0, f1);
            const float se0 = see[2 * p], se1 = see[2 * p + 1];
            float t;
            t = __fsub_rn(__fadd_rn(sxx0, se0), 2.0f * d0);
            if (t < bd0) { bd0 = t; bj0 = 2 * p; }
            t = __fsub_rn(__fadd_rn(sxx0, se1), 2.0f * d1);
            if (t < bd0) { bd0 = t; bj0 = 2 * p + 1; }
            t = __fsub_rn(__fadd_rn(sxx1, se0), 2.0f * f0);
            if (t < bd1) { bd1 = t; bj1 = 2 * p; }
            t = __fsub_rn(__fadd_rn(sxx1, se1), 2.0f * f1);
            if (t < bd1) { bd1 = t; bj1 = 2 * p + 1; }
        }

        if (v0) out[(size_t)n * EDIM + r0] = (float)bj0;
        if (v1) out[(size_t)n * EDIM + r1] = (float)bj1;

        // Phase 2: straight-through out = x + (q - x) (reference rounding) + loss.
        const float4* er0 = reinterpret_cast<const float4*>(e + (size_t)bj0 * EDIM);
        const float4* er1 = reinterpret_cast<const float4*>(e + (size_t)bj1 * EDIM);
        float4* oq0 = reinterpret_cast<float4*>(out + (size_t)r0 * EDIM);
        float4* oq1 = reinterpret_cast<float4*>(out + (size_t)r1 * EDIM);
        #pragma unroll 1
        for (int k0 = 0; k0 < EDIM / 4; ++k0) {
            if (v0) {
                const float4 q  = __ldg(er0 + k0);
                const float4 xv = __ldg(xr0 + k0);
                float dx = __fsub_rn(q.x, xv.x), dy = __fsub_rn(q.y, xv.y);
                float dz = __fsub_rn(q.z, xv.z), dw = __fsub_rn(q.w, xv.w);
                lsum = fmaf(dx, dx, lsum); lsum = fmaf(dy, dy, lsum);
                lsum = fmaf(dz, dz, lsum); lsum = fmaf(dw, dw, lsum);
                float4 o;
                o.x = __fadd_rn(xv.x, dx); o.y = __fadd_rn(xv.y, dy);
                o.z = __fadd_rn(xv.z, dz); o.w = __fadd_rn(xv.w, dw);
                oq0[k0] = o;
            }
            if (v1) {
                const float4 q  = __ldg(er1 + k0);
                const float4 xv = __ldg(xr1 + k0);
                float dx = __fsub_rn(q.x, xv.x), dy = __fsub_rn(q.y, xv.y);
                float dz = __fsub_rn(q.z, xv.z), dw = __fsub_rn(q.w, xv.w);
                lsum = fmaf(dx, dx, lsum); lsum = fmaf(dy, dy, lsum);
                lsum = fmaf(dz, dz, lsum); lsum = fmaf(dw, dw, lsum);
                float4 o;
                o.x = __fadd_rn(xv.x, dx); o.y = __fadd_rn(xv.y, dy);
                o.z = __fadd_rn(xv.z, dz); o.w = __fadd_rn(xv.w, dw);
                oq1[k0] = o;
            }
        }
    }

    // Block loss reduction
    #pragma unroll
    for (int off = 16; off > 0; off >>= 1)
        lsum += __shfl_down_sync(0xffffffffu, lsum, off);
    if ((tid & 31) == 0) wsum[tid >> 5] = lsum;
    __syncthreads();

    if (tid == 0) {
        float bs = wsum[0] + wsum[1] + wsum[2] + wsum[3];
        atomicAdd(&g_loss_sum, (double)bs);
        __threadfence();
        unsigned int prev = atomicAdd(&g_done, 1u);
        if (prev == gridDim.x - 1) {               // last block finalizes
            __threadfence();
            double total = atomicAdd(&g_loss_sum, 0.0);
            double mean = total / ((double)n * (double)EDIM);
            out[(size_t)n * EDIM + n]     = (float)(1.25 * mean);  // (1+BETA)*mean
            out[(size_t)n * EDIM + n + 1] = 0.0f;                  // contrastloss
            g_loss_sum = 0.0;                      // re-arm for next graph replay
            g_done = 0u;
            __threadfence();
        }
    }
}

extern "C" void kernel_launch(void* const* d_in, const int* in_sizes, int n_in,
                              void* d_out, int out_size) {
    (void)n_in; (void)out_size;
    const float* x = (const float*)d_in[0];   // inputs  [N, 192] fp32
    const float* e = (const float*)d_in[1];   // embed_w [50, 192] fp32
    float* out = (float*)d_out;               // [N*192 | N | 1 | 1] fp32
    const int n = in_sizes[0] / EDIM;

    const int blocks = (n + 255) / 256;       // 256 rows per block (2/thread)
    vq_main_kernel<<<blocks, 128>>>(x, e, out, n);
}